// round 1
// baseline (speedup 1.0000x reference)
#include <cuda_runtime.h>
#include <cstdint>
#include <cstddef>

#define EMB   768
#define HEADS 12
#define QKV   9216
#define FFD   3072
#define TOK   4096   /* B*T */
#define SEQ   2048

// ---------------- scratch (static device globals; no allocation) ----------------
__device__ float g_h [(size_t)TOK*EMB];
__device__ float g_q [(size_t)TOK*QKV];
__device__ float g_k [(size_t)TOK*QKV];
__device__ float g_v [(size_t)TOK*QKV];
__device__ float g_s [(size_t)2*HEADS*SEQ*SEQ];
__device__ float g_y [(size_t)TOK*QKV];
__device__ float g_x2[(size_t)TOK*EMB];
__device__ float g_ff[(size_t)TOK*FFD];

// ---------------- helpers ----------------
__device__ __forceinline__ uint32_t f2tf(float x){
    uint32_t r; asm("cvt.rna.tf32.f32 %0, %1;" : "=r"(r) : "f"(x)); return r;
}
__device__ __forceinline__ void cp16(void* sdst, const void* gsrc){
    unsigned d = (unsigned)__cvta_generic_to_shared(sdst);
    asm volatile("cp.async.cg.shared.global [%0], [%1], 16;" :: "r"(d), "l"(gsrc));
}
__device__ __forceinline__ void cp_commit(){ asm volatile("cp.async.commit_group;"); }
__device__ __forceinline__ void cp_wait0(){ asm volatile("cp.async.wait_group 0;"); }
__device__ __forceinline__ void cp_wait1(){ asm volatile("cp.async.wait_group 1;"); }

__device__ __forceinline__ void mma8(float* d, const uint32_t* a, const uint32_t* b){
    asm volatile(
      "mma.sync.aligned.m16n8k8.row.col.f32.tf32.tf32.f32 "
      "{%0,%1,%2,%3},{%4,%5,%6,%7},{%8,%9},{%0,%1,%2,%3};"
      : "+f"(d[0]), "+f"(d[1]), "+f"(d[2]), "+f"(d[3])
      : "r"(a[0]), "r"(a[1]), "r"(a[2]), "r"(a[3]), "r"(b[0]), "r"(b[1]));
}
__device__ __forceinline__ float gelu_f(float x){ return x * normcdff(x); }

// ---------------- GEMM ----------------
// C[M,N] = A[M,K] @ op(B), op(B) = B[K,N] (BT=false) or B[N,K]^T (BT=true)
// EPI: 0 none, 1 bias+resid, 2 bias+gelu
// CAUSAL: 0 none, 1 skip fully-masked n-blocks (scores), 2 K-limit to m0+BM (P@V)
#define BM 128
#define BN 128
#define BKK 16
#define GT 256

template<bool BT, int EPI, int CAUSAL>
__global__ __launch_bounds__(GT)
void gemm_tf32(const float* __restrict__ A, const float* __restrict__ B, float* __restrict__ C,
               int K, int lda, int ldb, int ldc,
               long long sA1, long long sA2, long long sB1, long long sB2,
               long long sC1, long long sC2, int zdiv,
               const float* __restrict__ bias, const float* __restrict__ resid, int ldr)
{
    const int m0 = blockIdx.y * BM;
    const int n0 = blockIdx.x * BN;
    if (CAUSAL == 1 && n0 >= m0 + BM) return;   // fully above the diagonal

    const int z  = blockIdx.z;
    const int zb = z / zdiv, zh = z - zb*zdiv;
    A += zb*sA1 + zh*sA2 + (size_t)m0*lda;
    B += zb*sB1 + zh*sB2;
    if (BT) B += (size_t)n0*ldb; else B += n0;
    C += zb*sC1 + zh*sC2 + (size_t)m0*ldc + n0;
    if (EPI >= 1) bias  += n0;
    if (EPI == 1) resid += (size_t)m0*ldr + n0;

    int Keff = K;
    if (CAUSAL == 2){ int kl = m0 + BM; Keff = kl < K ? kl : K; }
    const int nk = Keff / BKK;

    __shared__ float As[2][BM][BKK+4];                 // [128][20] — conflict-free frag loads
    constexpr int BSTR = BT ? (BKK+4) : (BN+8);        // 20 or 136
    constexpr int BSZ  = BT ? BM*(BKK+4) : BKK*(BN+8);
    __shared__ float Bs[2][BSZ];

    const int t    = threadIdx.x;
    const int lane = t & 31;
    const int warp = t >> 5;
    const int wm   = warp & 1;      // 2 warps in M
    const int wn   = warp >> 1;     // 4 warps in N
    const int rb   = wm*64 + (lane >> 2);
    const int cb   = wn*32 + (lane >> 2);
    const int kq   = lane & 3;

    auto copy_tile = [&](int kt, int bu){
        const int k0 = kt * BKK;
        #pragma unroll
        for (int i = 0; i < 2; ++i){
            int f = t + i*GT;
            int row = f >> 2, k4 = (f & 3) << 2;
            cp16(&As[bu][row][k4], A + (size_t)row*lda + k0 + k4);
        }
        #pragma unroll
        for (int i = 0; i < 2; ++i){
            int f = t + i*GT;
            if (BT){
                int row = f >> 2, k4 = (f & 3) << 2;
                cp16(&Bs[bu][row*BSTR + k4], B + (size_t)row*ldb + k0 + k4);
            } else {
                int kr = f >> 5, n4 = (f & 31) << 2;
                cp16(&Bs[bu][kr*BSTR + n4], B + (size_t)(k0+kr)*ldb + n4);
            }
        }
    };

    float acc[4][4][4];
    #pragma unroll
    for (int mt=0; mt<4; mt++)
        #pragma unroll
        for (int nt=0; nt<4; nt++)
            #pragma unroll
            for (int i=0;i<4;i++) acc[mt][nt][i]=0.f;

    copy_tile(0, 0); cp_commit();

    for (int kt = 0; kt < nk; ++kt){
        if (kt + 1 < nk){ copy_tile(kt+1, (kt+1)&1); cp_commit(); cp_wait1(); }
        else            { cp_wait0(); }
        __syncthreads();
        const int bu = kt & 1;
        #pragma unroll
        for (int ks = 0; ks < 2; ++ks){
            const int kk = ks*8 + kq;
            uint32_t af[4][4];
            #pragma unroll
            for (int mt=0; mt<4; mt++){
                int r = rb + mt*16;
                af[mt][0] = f2tf(As[bu][r  ][kk  ]);
                af[mt][1] = f2tf(As[bu][r+8][kk  ]);
                af[mt][2] = f2tf(As[bu][r  ][kk+4]);
                af[mt][3] = f2tf(As[bu][r+8][kk+4]);
            }
            uint32_t bf[4][2];
            #pragma unroll
            for (int nt=0; nt<4; nt++){
                int c = cb + nt*8;
                if (BT){
                    bf[nt][0] = f2tf(Bs[bu][c*BSTR + kk  ]);
                    bf[nt][1] = f2tf(Bs[bu][c*BSTR + kk+4]);
                } else {
                    bf[nt][0] = f2tf(Bs[bu][(kk  )*BSTR + c]);
                    bf[nt][1] = f2tf(Bs[bu][(kk+4)*BSTR + c]);
                }
            }
            #pragma unroll
            for (int mt=0; mt<4; mt++)
                #pragma unroll
                for (int nt=0; nt<4; nt++)
                    mma8(acc[mt][nt], af[mt], bf[nt]);
        }
        __syncthreads();
    }

    // epilogue
    const int ce = (lane & 3) * 2;
    #pragma unroll
    for (int mt=0; mt<4; mt++){
        const int r0 = wm*64 + mt*16 + (lane>>2);
        #pragma unroll
        for (int nt=0; nt<4; nt++){
            const int c = wn*32 + nt*8 + ce;
            float v0=acc[mt][nt][0], v1=acc[mt][nt][1], v2=acc[mt][nt][2], v3=acc[mt][nt][3];
            if (EPI >= 1){
                float bb0 = bias[c], bb1 = bias[c+1];
                v0+=bb0; v1+=bb1; v2+=bb0; v3+=bb1;
            }
            if (EPI == 1){
                v0 += resid[(size_t) r0   *ldr + c    ];
                v1 += resid[(size_t) r0   *ldr + c + 1];
                v2 += resid[(size_t)(r0+8)*ldr + c    ];
                v3 += resid[(size_t)(r0+8)*ldr + c + 1];
            }
            if (EPI == 2){ v0=gelu_f(v0); v1=gelu_f(v1); v2=gelu_f(v2); v3=gelu_f(v3); }
            *(float2*)(C + (size_t) r0   *ldc + c) = make_float2(v0,v1);
            *(float2*)(C + (size_t)(r0+8)*ldc + c) = make_float2(v2,v3);
        }
    }
}

// ---------------- LayerNorm ----------------
__global__ __launch_bounds__(256)
void ln_kernel(const float* __restrict__ x, const float* __restrict__ g,
               const float* __restrict__ b, float* __restrict__ o)
{
    __shared__ float sh[16];
    const int row = blockIdx.x;
    const float* xr = x + (size_t)row*EMB;
    const int t = threadIdx.x;
    float v0 = xr[t], v1 = xr[t+256], v2 = xr[t+512];
    float s  = v0+v1+v2;
    float s2 = v0*v0 + v1*v1 + v2*v2;
    #pragma unroll
    for (int off=16; off; off>>=1){
        s  += __shfl_down_sync(0xffffffffu, s,  off);
        s2 += __shfl_down_sync(0xffffffffu, s2, off);
    }
    const int lane = t&31, wid = t>>5;
    if (lane==0){ sh[wid]=s; sh[8+wid]=s2; }
    __syncthreads();
    if (t==0){
        float a=0.f, c=0.f;
        #pragma unroll
        for (int i=0;i<8;i++){ a+=sh[i]; c+=sh[8+i]; }
        sh[0]=a; sh[8]=c;
    }
    __syncthreads();
    const float mu  = sh[0]*(1.f/EMB);
    const float var = sh[8]*(1.f/EMB) - mu*mu;
    const float rs  = rsqrtf(var + 1e-5f);
    float* orow = o + (size_t)row*EMB;
    orow[t]     = (v0-mu)*rs*g[t]     + b[t];
    orow[t+256] = (v1-mu)*rs*g[t+256] + b[t+256];
    orow[t+512] = (v2-mu)*rs*g[t+512] + b[t+512];
}

// ---------------- causal softmax (applies 1/sqrt(QKV) scale, zeros masked cols) ----------------
__global__ __launch_bounds__(256)
void softmax_kernel(float* __restrict__ S)
{
    __shared__ float shm[8];
    __shared__ float shs[8];
    const int i = blockIdx.x;
    const long long z = blockIdx.y;
    float* row = S + (z*(long long)SEQ + i) * (long long)SEQ;
    const int L = i + 1;
    const int t = threadIdx.x;
    const int lane = t & 31, wid = t >> 5;
    const float scale = 1.0f/96.0f;   // 1/sqrt(9216)

    float vals[8];
    float mx = -1e30f;
    #pragma unroll
    for (int u=0; u<8; u++){
        int j = t + (u<<8);
        float v = (j < L) ? row[j]*scale : -1e30f;
        vals[u] = v;
        mx = fmaxf(mx, v);
    }
    #pragma unroll
    for (int o=16; o; o>>=1) mx = fmaxf(mx, __shfl_xor_sync(0xffffffffu, mx, o));
    if (lane==0) shm[wid] = mx;
    __syncthreads();
    float m = shm[0];
    #pragma unroll
    for (int w=1; w<8; w++) m = fmaxf(m, shm[w]);

    float sum = 0.f;
    #pragma unroll
    for (int u=0; u<8; u++){
        int j = t + (u<<8);
        float e = (j < L) ? __expf(vals[u]-m) : 0.f;
        vals[u] = e;
        sum += e;
    }
    #pragma unroll
    for (int o=16; o; o>>=1) sum += __shfl_xor_sync(0xffffffffu, sum, o);
    if (lane==0) shs[wid] = sum;
    __syncthreads();
    float tot = 0.f;
    #pragma unroll
    for (int w=0; w<8; w++) tot += shs[w];
    const float inv = 1.0f / tot;
    #pragma unroll
    for (int u=0; u<8; u++){
        int j = t + (u<<8);
        row[j] = vals[u]*inv;
    }
}

// ---------------- launch ----------------
extern "C" void kernel_launch(void* const* d_in, const int* in_sizes, int n_in,
                              void* d_out, int out_size)
{
    const float* x   = (const float*)d_in[0];
    const float* Wq  = (const float*)d_in[1];
    const float* Wk  = (const float*)d_in[2];
    const float* Wv  = (const float*)d_in[3];
    const float* Wo  = (const float*)d_in[4];
    const float* bo  = (const float*)d_in[5];
    const float* W1  = (const float*)d_in[6];
    const float* b1  = (const float*)d_in[7];
    const float* W2  = (const float*)d_in[8];
    const float* b2  = (const float*)d_in[9];
    const float* g1  = (const float*)d_in[10];
    const float* be1 = (const float*)d_in[11];
    const float* g2  = (const float*)d_in[12];
    const float* be2 = (const float*)d_in[13];
    float* out = (float*)d_out;

    float *h,*q,*k,*v,*s,*y,*x2,*ff;
    cudaGetSymbolAddress((void**)&h,  g_h);
    cudaGetSymbolAddress((void**)&q,  g_q);
    cudaGetSymbolAddress((void**)&k,  g_k);
    cudaGetSymbolAddress((void**)&v,  g_v);
    cudaGetSymbolAddress((void**)&s,  g_s);
    cudaGetSymbolAddress((void**)&y,  g_y);
    cudaGetSymbolAddress((void**)&x2, g_x2);
    cudaGetSymbolAddress((void**)&ff, g_ff);

    // h = LN1(x)
    ln_kernel<<<TOK,256>>>(x, g1, be1, h);

    // q/k/v = h @ W{q,k,v}    [4096 x 9216], K=768
    dim3 gqkv(QKV/BN, TOK/BM, 1);
    gemm_tf32<false,0,0><<<gqkv,GT>>>(h, Wq, q, EMB, EMB, QKV, QKV,
                                      0,0,0,0,0,0, 1, nullptr, nullptr, 0);
    gemm_tf32<false,0,0><<<gqkv,GT>>>(h, Wk, k, EMB, EMB, QKV, QKV,
                                      0,0,0,0,0,0, 1, nullptr, nullptr, 0);
    gemm_tf32<false,0,0><<<gqkv,GT>>>(h, Wv, v, EMB, EMB, QKV, QKV,
                                      0,0,0,0,0,0, 1, nullptr, nullptr, 0);

    // scores[z] = q_z @ k_z^T, z = b*HEADS + h   (causal block skip)
    dim3 gs(SEQ/BN, SEQ/BM, 2*HEADS);
    gemm_tf32<true,0,1><<<gs,GT>>>(q, k, s, EMB, QKV, QKV, SEQ,
        (long long)SEQ*QKV, (long long)EMB,
        (long long)SEQ*QKV, (long long)EMB,
        (long long)HEADS*SEQ*SEQ, (long long)SEQ*SEQ, HEADS,
        nullptr, nullptr, 0);

    // causal softmax (also zeroes masked columns so P@V can read full rows)
    softmax_kernel<<<dim3(SEQ, 2*HEADS),256>>>(s);

    // y[z] = P_z @ V_z   (K limited to causal extent)
    dim3 gpv(EMB/BN, SEQ/BM, 2*HEADS);
    gemm_tf32<false,0,2><<<gpv,GT>>>(s, v, y, SEQ, SEQ, QKV, QKV,
        (long long)HEADS*SEQ*SEQ, (long long)SEQ*SEQ,
        (long long)SEQ*QKV, (long long)EMB,
        (long long)SEQ*QKV, (long long)EMB, HEADS,
        nullptr, nullptr, 0);

    // x2 = y @ Wo + bo + x
    dim3 go(EMB/BN, TOK/BM, 1);
    gemm_tf32<false,1,0><<<go,GT>>>(y, Wo, x2, QKV, QKV, EMB, EMB,
                                    0,0,0,0,0,0, 1, bo, x, EMB);

    // h = LN2(x2)
    ln_kernel<<<TOK,256>>>(x2, g2, be2, h);

    // ff = gelu(h @ W1 + b1)
    dim3 gf(FFD/BN, TOK/BM, 1);
    gemm_tf32<false,2,0><<<gf,GT>>>(h, W1, ff, EMB, EMB, FFD, FFD,
                                    0,0,0,0,0,0, 1, b1, nullptr, 0);

    // out = ff @ W2 + b2 + x2
    gemm_tf32<false,1,0><<<go,GT>>>(ff, W2, out, FFD, FFD, EMB, EMB,
                                    0,0,0,0,0,0, 1, b2, x2, EMB);
}